// round 13
// baseline (speedup 1.0000x reference)
#include <cuda_runtime.h>

// q = prod_i cos(pi/2 + 2*x_i) = prod_i sin(2*x_i)   (8 factors, (-1)^8 cancels)
// out[i] = { scale*q, -scale*q }
// Persistent grid-stride kernel: one wave, 2 pair-indices (4 rows) per iteration.

#define NUM_SMS        148
#define BLOCKS_PER_SM  8
#define THREADS        256

__device__ __forceinline__ float row_prod(float4 a, float4 b)
{
    float q = __sinf(2.0f * a.x);
    q *= __sinf(2.0f * a.y);
    q *= __sinf(2.0f * a.z);
    q *= __sinf(2.0f * a.w);
    q *= __sinf(2.0f * b.x);
    q *= __sinf(2.0f * b.y);
    q *= __sinf(2.0f * b.z);
    q *= __sinf(2.0f * b.w);
    return q;
}

__global__ void __launch_bounds__(THREADS, BLOCKS_PER_SM) qnn_kernel3(
    const float4* __restrict__ x,      // [B, 8] viewed as float4[B*2]
    const float* __restrict__ scale,   // scalar on device
    float4* __restrict__ out,          // [B/2] x {s*q, -s*q, s*q', -s*q'}
    int Bpairs)                        // B/2
{
    const int stride = gridDim.x * blockDim.x;       // threads in grid
    const float s = __ldg(scale);

    int i = blockIdx.x * blockDim.x + threadIdx.x;

    // Main loop: 2 pair-indices per iteration (4 rows, 8x LDG.128, 2x STG.128)
    for (; i + stride < Bpairs; i += 2 * stride) {
        int j = i + stride;

        float4 a0 = __ldcs(&x[4 * i + 0]);
        float4 a1 = __ldcs(&x[4 * i + 1]);
        float4 a2 = __ldcs(&x[4 * i + 2]);
        float4 a3 = __ldcs(&x[4 * i + 3]);
        float4 b0 = __ldcs(&x[4 * j + 0]);
        float4 b1 = __ldcs(&x[4 * j + 1]);
        float4 b2 = __ldcs(&x[4 * j + 2]);
        float4 b3 = __ldcs(&x[4 * j + 3]);

        float q0 = row_prod(a0, a1);
        float q1 = row_prod(a2, a3);
        float q2 = row_prod(b0, b1);
        float q3 = row_prod(b2, b3);

        __stcs(&out[i], make_float4(s * q0, -s * q0, s * q1, -s * q1));
        __stcs(&out[j], make_float4(s * q2, -s * q2, s * q3, -s * q3));
    }

    // Tail: one pair-index at a time
    for (; i < Bpairs; i += stride) {
        float4 a0 = __ldcs(&x[4 * i + 0]);
        float4 a1 = __ldcs(&x[4 * i + 1]);
        float4 a2 = __ldcs(&x[4 * i + 2]);
        float4 a3 = __ldcs(&x[4 * i + 3]);

        float q0 = row_prod(a0, a1);
        float q1 = row_prod(a2, a3);

        __stcs(&out[i], make_float4(s * q0, -s * q0, s * q1, -s * q1));
    }
}

extern "C" void kernel_launch(void* const* d_in, const int* in_sizes, int n_in,
                              void* d_out, int out_size)
{
    const float* x     = (const float*)d_in[0];   // [B, 8]
    // d_in[1] = weights (unused, n_layers = 0)
    const float* scale = (const float*)d_in[2];   // scalar

    int B = in_sizes[0] / 8;
    int Bpairs = B / 2;

    int blocks = NUM_SMS * BLOCKS_PER_SM;          // single persistent wave
    qnn_kernel3<<<blocks, THREADS>>>((const float4*)x, scale, (float4*)d_out, Bpairs);
}

// round 14
// speedup vs baseline: 1.0890x; 1.0890x over previous
#include <cuda_runtime.h>

// q = prod_i cos(pi/2 + 2*x_i) = prod_i sin(2*x_i)   (8 factors, (-1)^8 cancels)
// out[i] = { scale*q, -scale*q }
// Flat grid (HW-scheduled), 2 rows per thread, streaming cache hints:
// 4x LDG.128 (evict-first) front-batched, 1x STG.128 (evict-first).

#define THREADS 256

__device__ __forceinline__ float row_prod(float4 a, float4 b)
{
    float q = __sinf(2.0f * a.x);
    q *= __sinf(2.0f * a.y);
    q *= __sinf(2.0f * a.z);
    q *= __sinf(2.0f * a.w);
    q *= __sinf(2.0f * b.x);
    q *= __sinf(2.0f * b.y);
    q *= __sinf(2.0f * b.z);
    q *= __sinf(2.0f * b.w);
    return q;
}

__global__ void __launch_bounds__(THREADS) qnn_kernel4(
    const float4* __restrict__ x,      // [B, 8] viewed as float4[B*2]
    const float* __restrict__ scale,   // scalar on device
    float4* __restrict__ out,          // [B/2] x {s*q0, -s*q0, s*q1, -s*q1}
    int Bpairs)                        // B/2
{
    int i = blockIdx.x * blockDim.x + threadIdx.x;
    if (i >= Bpairs) return;

    // Front-batch all 4 global loads, evict-first (touch-once stream)
    float4 a0 = __ldcs(&x[4 * i + 0]);
    float4 a1 = __ldcs(&x[4 * i + 1]);
    float4 b0 = __ldcs(&x[4 * i + 2]);
    float4 b1 = __ldcs(&x[4 * i + 3]);

    float q0 = row_prod(a0, a1);
    float q1 = row_prod(b0, b1);

    float s = __ldg(scale);
    __stcs(&out[i], make_float4(s * q0, -s * q0, s * q1, -s * q1));
}

extern "C" void kernel_launch(void* const* d_in, const int* in_sizes, int n_in,
                              void* d_out, int out_size)
{
    const float* x     = (const float*)d_in[0];   // [B, 8]
    // d_in[1] = weights (unused, n_layers = 0)
    const float* scale = (const float*)d_in[2];   // scalar

    int B = in_sizes[0] / 8;
    int Bpairs = B / 2;

    int blocks = (Bpairs + THREADS - 1) / THREADS;
    qnn_kernel4<<<blocks, THREADS>>>((const float4*)x, scale, (float4*)d_out, Bpairs);
}